// round 10
// baseline (speedup 1.0000x reference)
#include <cuda_runtime.h>
#include <cuda_fp16.h>
#include <cstdint>

#define NV 8000
#define NVT 20000
#define C_TOTAL 960
#define KPAD_SUM 4224
#define A_ELEMS 3145728   // sum M*Kpad

// ---------------- scratch (__device__ globals; allocation-free rule) ----------------
__device__ __align__(16) __half g_ahi[A_ELEMS];                  // fp16 fmap
__device__ __align__(16) __half g_bhi[(size_t)NV * KPAD_SUM];    // [8000, Kp] K-major fp16
__device__ __align__(16) float g_wsel[(size_t)C_TOTAL * NV];

// ---------------- roi dtype detect (int64 vs int32; values < 20000) ----------------
__device__ __forceinline__ bool roi_is64(const int* __restrict__ r32) {
    int acc = 0;
#pragma unroll
    for (int i = 1; i < 32; i += 2) acc |= r32[i];
    return acc == 0;
}

// ---------------- prep kernels (R8 versions — proven fast) ----------------
__global__ void split_all(const float* __restrict__ f0, const float* __restrict__ f1,
                          const float* __restrict__ f2, const float* __restrict__ f3) {
    int idx = blockIdx.x * 256 + threadIdx.x;
    const float* f; int K, Kpad, base;
    if (idx < 1605632)      { f = f0; K = 3136; Kpad = 3136; base = 0; }
    else if (idx < 2424832) { f = f1; K = 784;  Kpad = 800;  base = 1605632; }
    else if (idx < 2883584) { f = f2; K = 196;  Kpad = 224;  base = 2424832; }
    else if (idx < A_ELEMS) { f = f3; K = 49;   Kpad = 64;   base = 2883584; }
    else return;
    int local = idx - base;
    int m = local / Kpad, k = local - m * Kpad;
    float x = (k < K) ? f[(size_t)m * K + k] : 0.0f;
    g_ahi[idx] = __float2half_rn(x);
}

__global__ void gather_tr_all(const float* __restrict__ r0, const float* __restrict__ r1,
                              const float* __restrict__ r2, const float* __restrict__ r3,
                              const int* __restrict__ roi) {
    __shared__ float tile[32][257];
    const int pb = blockIdx.x;
    const float* rf; int K, Kpad, pbase; size_t bOff;
    if (pb < 98)       { rf = r0; K = 3136; Kpad = 3136; bOff = 0;        pbase = 0; }
    else if (pb < 123) { rf = r1; K = 784;  Kpad = 800;  bOff = 25088000; pbase = 98; }
    else if (pb < 130) { rf = r2; K = 196;  Kpad = 224;  bOff = 31488000; pbase = 123; }
    else               { rf = r3; K = 49;   Kpad = 64;   bOff = 33280000; pbase = 130; }
    const int p0 = (pb - pbase) * 32;
    const int v0 = blockIdx.y * 256;
    const int tid = threadIdx.x;
    const bool is64 = roi_is64(roi);

    int vr = v0 + tid;
    int ri = (vr < NV) ? (is64 ? roi[2 * vr] : roi[vr]) : 0;
#pragma unroll 4
    for (int i = 0; i < 32; i++) {
        int p = p0 + i;
        float x = 0.0f;
        if (p < K && vr < NV) {
            x = rf[(size_t)p * NVT + ri];
            x = (x > 0.0f) ? x : 0.01f * x;
        }
        tile[i][tid] = x;
    }
    __syncthreads();

    const int pl = tid & 31;
    const int vb = tid >> 5;
#pragma unroll 4
    for (int i = 0; i < 32; i++) {
        int vloc = vb + (i << 3);
        int v = v0 + vloc;
        if (v < NV)
            g_bhi[bOff + (size_t)v * Kpad + p0 + pl] = __float2half_rn(tile[pl][vloc]);
    }
}

__global__ void gather_w_all(const float* __restrict__ w0, const float* __restrict__ w1,
                             const float* __restrict__ w2, const float* __restrict__ w3,
                             const int* __restrict__ roi) {
    const bool is64 = roi_is64(roi);
    long long idx = (long long)blockIdx.x * 256 + threadIdx.x;
    if (idx >= (long long)C_TOTAL * NV) return;
    int v = (int)(idx % NV);
    int c = (int)(idx / NV);
    const float* w; int lc;
    if (c < 64)       { w = w0; lc = c; }
    else if (c < 192) { w = w1; lc = c - 64; }
    else if (c < 448) { w = w2; lc = c - 192; }
    else              { w = w3; lc = c - 448; }
    int ri = is64 ? roi[2 * v] : roi[v];
    g_wsel[(size_t)c * NV + v] = w[(size_t)lc * NVT + (size_t)ri];
}

// ---------------- fused fp16 mma.sync GEMM: 4 warps x 64x64 warp tiles ----------------
// out[b, c, v] = (A @ B^T)[m, v] * wsel ; BM=128, BN=128, BK=32; 128 threads.
// 4-stage cp.async pipeline, one __syncthreads per k-iteration.

#define STAGE_BYTES 16384
#define A_HI_OFF 0
#define B_HI_OFF 8192
#define SMEM_TOTAL (4 * STAGE_BYTES)   // 64 KB

__device__ __forceinline__ uint32_t smem_u32(const void* p) {
    uint32_t a;
    asm("{ .reg .u64 t; cvta.to.shared.u64 t, %1; cvt.u32.u64 %0, t; }" : "=r"(a) : "l"(p));
    return a;
}
// 64B rows (32 halves); chunk = 16B unit; conflict-free for ldmatrix
__device__ __forceinline__ uint32_t swz(uint32_t base, int row, int chunk) {
    return base + (uint32_t)(row * 64 + (chunk ^ ((row >> 1) & 3)) * 16);
}
__device__ __forceinline__ void cp16(uint32_t dst, const void* src, bool v) {
    asm volatile("cp.async.cg.shared.global [%0], [%1], 16, %2;"
                 :: "r"(dst), "l"(src), "r"(v ? 16 : 0));
}
#define CP_COMMIT() asm volatile("cp.async.commit_group;" ::: "memory")
#define CP_WAIT2()  asm volatile("cp.async.wait_group 2;" ::: "memory")

#define LDSM4(r0, r1, r2, r3, a) \
    asm volatile("ldmatrix.sync.aligned.m8n8.x4.shared.b16 {%0,%1,%2,%3}, [%4];" \
                 : "=r"(r0), "=r"(r1), "=r"(r2), "=r"(r3) : "r"(a))

#define MMA(d, a, b0_, b1_) \
    asm volatile("mma.sync.aligned.m16n8k16.row.col.f32.f16.f16.f32 " \
                 "{%0,%1,%2,%3}, {%4,%5,%6,%7}, {%8,%9}, {%0,%1,%2,%3};" \
                 : "+f"((d)[0]), "+f"((d)[1]), "+f"((d)[2]), "+f"((d)[3]) \
                 : "r"((a)[0]), "r"((a)[1]), "r"((a)[2]), "r"((a)[3]), "r"(b0_), "r"(b1_))

__global__ void __launch_bounds__(128, 2)
gemm_all(float* __restrict__ out)
{
    extern __shared__ char smem[];
    const uint32_t sb = smem_u32(smem);
    const int tid = threadIdx.x;
    const int lane = tid & 31;
    const int w = tid >> 5;         // 0..3
    const int wm = w >> 1;          // 0..1 (m)
    const int wn = w & 1;           // 0..1 (n)

    // tile decode: layer-0 tiles first (longest-job-first)
    const int t = blockIdx.x;
    int Kpad, cShift, cOff, mtiles, base; size_t aOff, bOff;
    if (t < 252)       { base = 0;    mtiles = 4;  Kpad = 3136; aOff = 0;       bOff = 0;        cShift = 6; cOff = 0; }
    else if (t < 756)  { base = 252;  mtiles = 8;  Kpad = 800;  aOff = 1605632; bOff = 25088000; cShift = 7; cOff = 64; }
    else if (t < 1764) { base = 756;  mtiles = 16; Kpad = 224;  aOff = 2424832; bOff = 31488000; cShift = 8; cOff = 192; }
    else               { base = 1764; mtiles = 32; Kpad = 64;   aOff = 2883584; bOff = 33280000; cShift = 9; cOff = 448; }
    const int local = t - base;
    const int bm = (local % mtiles) * 128;   // m fastest -> B v-tile L2 reuse
    const int bn = (local / mtiles) * 128;

    const __half* __restrict__ Ahi = g_ahi + aOff;
    const __half* __restrict__ Bhi = g_bhi + bOff;

    const int nkt = Kpad >> 5;

    // ---- stage loader: 512 chunk-ids x 2 arrays, 8 cp.async per thread ----
    auto load_stage = [&](int kt, int buf) {
        const uint32_t s = sb + buf * STAGE_BYTES;
        const int k0 = kt << 5;
#pragma unroll
        for (int q = 0; q < 4; q++) {
            int cid = q * 128 + tid;
            int row = cid >> 2, ch = cid & 3;
            size_t ga = (size_t)(bm + row) * Kpad + k0 + ch * 8;
            cp16(swz(s + A_HI_OFF, row, ch), Ahi + ga, true);
            int n = bn + row;
            bool v = n < NV;
            size_t gb = v ? ((size_t)n * Kpad + k0 + ch * 8) : 0;
            cp16(swz(s + B_HI_OFF, row, ch), Bhi + gb, v);
        }
    };

    float acc[4][8][4];
#pragma unroll
    for (int i = 0; i < 4; i++)
#pragma unroll
        for (int j = 0; j < 8; j++)
#pragma unroll
            for (int q = 0; q < 4; q++) acc[i][j][q] = 0.0f;

    // prologue: fill 3 stages
    load_stage(0, 0); CP_COMMIT();
    if (nkt > 1) load_stage(1, 1);
    CP_COMMIT();
    if (nkt > 2) load_stage(2, 2);
    CP_COMMIT();

    const int mid = lane >> 3, r8 = lane & 7;

    for (int kt = 0; kt < nkt; kt++) {
        CP_WAIT2();          // stage kt complete
        __syncthreads();     // all warps past compute kt-1 -> stage (kt+3)&3 free
        if (kt + 3 < nkt) load_stage(kt + 3, (kt + 3) & 3);
        CP_COMMIT();

        const uint32_t s = sb + (kt & 3) * STAGE_BYTES;
#pragma unroll
        for (int ks = 0; ks < 2; ks++) {
            uint32_t ah[4][4], bh[4][4];
            // A frags: warp covers 64 m rows
            int arow = wm * 64 + (mid & 1) * 8 + r8;
            int ach = ks * 2 + (mid >> 1);
#pragma unroll
            for (int mi = 0; mi < 4; mi++)
                LDSM4(ah[mi][0], ah[mi][1], ah[mi][2], ah[mi][3],
                      swz(s + A_HI_OFF, arow + mi * 16, ach));
            // B frags: warp covers 64 n rows
            int brow = wn * 64 + (mid >> 1) * 8 + r8;
            int bch = ks * 2 + (mid & 1);
#pragma unroll
            for (int nj = 0; nj < 4; nj++)
                LDSM4(bh[nj][0], bh[nj][1], bh[nj][2], bh[nj][3],
                      swz(s + B_HI_OFF, brow + nj * 16, bch));
#pragma unroll
            for (int mi = 0; mi < 4; mi++) {
#pragma unroll
                for (int ni = 0; ni < 8; ni++) {
                    uint32_t* bp = &bh[ni >> 1][(ni & 1) * 2];
                    MMA(acc[mi][ni], ah[mi], bp[0], bp[1]);
                }
            }
        }
    }

    // ---- epilogue: scale by wsel, store ----
    const int tg = lane >> 2, tq = lane & 3;
    const int Cm1 = (1 << cShift) - 1;
#pragma unroll
    for (int mi = 0; mi < 4; mi++) {
#pragma unroll
        for (int h = 0; h < 2; h++) {
            int m = bm + wm * 64 + mi * 16 + h * 8 + tg;
            int bI = m >> cShift;
            int c = m & Cm1;
            float* orow = out + ((size_t)bI * C_TOTAL + cOff + c) * NV;
            const float* wrow = g_wsel + (size_t)(cOff + c) * NV;
#pragma unroll
            for (int ni = 0; ni < 8; ni++) {
                int col = bn + wn * 64 + ni * 8 + tq * 2;
                if (col < NV) {
                    float2 wv = *(const float2*)(wrow + col);
                    float2 o;
                    o.x = acc[mi][ni][h * 2 + 0] * wv.x;
                    o.y = acc[mi][ni][h * 2 + 1] * wv.y;
                    *(float2*)(orow + col) = o;
                }
            }
        }
    }
}

// ---------------- launch ----------------
extern "C" void kernel_launch(void* const* d_in, const int* in_sizes, int n_in,
                              void* d_out, int out_size) {
    static const int fsz[4] = {1605632, 802816, 401408, 200704};
    static const int rsz[4] = {62720000, 15680000, 3920000, 980000};
    static const int wsz[4] = {1280000, 2560000, 5120000, 10240000};

    const float* fmap[4] = {0, 0, 0, 0};
    const float* rfp[4]  = {0, 0, 0, 0};
    const float* wptr[4] = {0, 0, 0, 0};
    const int*   roi = 0;

    for (int i = 0; i < n_in; i++) {
        int s = in_sizes[i];
        if (s == NV) { roi = (const int*)d_in[i]; continue; }
        for (int l = 0; l < 4; l++) {
            if (s == fsz[l]) fmap[l] = (const float*)d_in[i];
            else if (s == rsz[l]) rfp[l]  = (const float*)d_in[i];
            else if (s == wsz[l]) wptr[l] = (const float*)d_in[i];
        }
    }

    float* out = (float*)d_out;

    cudaFuncSetAttribute(gemm_all, cudaFuncAttributeMaxDynamicSharedMemorySize, SMEM_TOTAL);

    split_all<<<A_ELEMS / 256, 256>>>(fmap[0], fmap[1], fmap[2], fmap[3]);          // 1
    gather_tr_all<<<dim3(132, 32), 256>>>(rfp[0], rfp[1], rfp[2], rfp[3], roi);     // 2
    gather_w_all<<<(int)(((long long)C_TOTAL * NV + 255) / 256), 256>>>(            // 3
        wptr[0], wptr[1], wptr[2], wptr[3], roi);
    gemm_all<<<3780, 128, SMEM_TOTAL>>>(out);                                        // 4 <- profiled
}

// round 11
// speedup vs baseline: 1.2710x; 1.2710x over previous
#include <cuda_runtime.h>
#include <cuda_fp16.h>
#include <cstdint>

#define NV 8000
#define NVT 20000
#define C_TOTAL 960
#define KPAD_SUM 4224
#define A_ELEMS 3145728   // sum M*Kpad

// ---------------- scratch (__device__ globals; allocation-free rule) ----------------
__device__ __align__(16) __half g_ahi[A_ELEMS];                  // fp16 fmap
__device__ __align__(16) __half g_bhi[(size_t)NV * KPAD_SUM];    // [8000, Kp] K-major fp16
__device__ __align__(16) float g_wsel[(size_t)C_TOTAL * NV];

// ---------------- roi dtype detect (int64 vs int32; values < 20000) ----------------
__device__ __forceinline__ bool roi_is64(const int* __restrict__ r32) {
    int acc = 0;
#pragma unroll
    for (int i = 1; i < 32; i += 2) acc |= r32[i];
    return acc == 0;
}

// ---------------- prep kernels ----------------
__global__ void split_all(const float* __restrict__ f0, const float* __restrict__ f1,
                          const float* __restrict__ f2, const float* __restrict__ f3) {
    int idx = blockIdx.x * 256 + threadIdx.x;
    const float* f; int K, Kpad, base;
    if (idx < 1605632)      { f = f0; K = 3136; Kpad = 3136; base = 0; }
    else if (idx < 2424832) { f = f1; K = 784;  Kpad = 800;  base = 1605632; }
    else if (idx < 2883584) { f = f2; K = 196;  Kpad = 224;  base = 2424832; }
    else if (idx < A_ELEMS) { f = f3; K = 49;   Kpad = 64;   base = 2883584; }
    else return;
    int local = idx - base;
    int m = local / Kpad, k = local - m * Kpad;
    float x = (k < K) ? f[(size_t)m * K + k] : 0.0f;
    g_ahi[idx] = __float2half_rn(x);
}

// gather + leaky_relu + transpose + fp16; MLP-maximized: 32 independent LDGs in flight
__global__ void gather_tr_all(const float* __restrict__ r0, const float* __restrict__ r1,
                              const float* __restrict__ r2, const float* __restrict__ r3,
                              const int* __restrict__ roi) {
    __shared__ float tile[32][257];
    const int pb = blockIdx.x;
    const float* rf; int K, Kpad, pbase; size_t bOff;
    if (pb < 98)       { rf = r0; K = 3136; Kpad = 3136; bOff = 0;        pbase = 0; }
    else if (pb < 123) { rf = r1; K = 784;  Kpad = 800;  bOff = 25088000; pbase = 98; }
    else if (pb < 130) { rf = r2; K = 196;  Kpad = 224;  bOff = 31488000; pbase = 123; }
    else               { rf = r3; K = 49;   Kpad = 64;   bOff = 33280000; pbase = 130; }
    const int p0 = (pb - pbase) * 32;
    const int v0 = blockIdx.y * 256;
    const int tid = threadIdx.x;
    const bool is64 = roi_is64(roi);

    const int vr = v0 + tid;
    const bool vok = vr < NV;
    const int ri = vok ? (is64 ? roi[2 * vr] : roi[vr]) : 0;
    const float* col = rf + ri;               // column base; rows stride NVT

    if (p0 + 32 <= K && vok) {
        // fast path: all 32 rows valid -> 32 independent loads, full MLP
        float x[32];
#pragma unroll
        for (int i = 0; i < 32; i++)
            x[i] = __ldg(col + (size_t)(p0 + i) * NVT);
#pragma unroll
        for (int i = 0; i < 32; i++)
            tile[i][tid] = (x[i] > 0.0f) ? x[i] : 0.01f * x[i];
    } else {
#pragma unroll
        for (int i = 0; i < 32; i++) {
            int p = p0 + i;
            float x = 0.0f;
            if (p < K && vok) {
                x = __ldg(col + (size_t)p * NVT);
                x = (x > 0.0f) ? x : 0.01f * x;
            }
            tile[i][tid] = x;
        }
    }
    __syncthreads();

    const int pl = tid & 31;
    const int vb = tid >> 5;
#pragma unroll
    for (int i = 0; i < 32; i++) {
        int vloc = vb + (i << 3);
        int v = v0 + vloc;
        if (v < NV)
            g_bhi[bOff + (size_t)v * Kpad + p0 + pl] = __float2half_rn(tile[pl][vloc]);
    }
}

__global__ void gather_w_all(const float* __restrict__ w0, const float* __restrict__ w1,
                             const float* __restrict__ w2, const float* __restrict__ w3,
                             const int* __restrict__ roi) {
    const bool is64 = roi_is64(roi);
    long long idx = (long long)blockIdx.x * 256 + threadIdx.x;
    if (idx >= (long long)C_TOTAL * NV) return;
    int v = (int)(idx % NV);
    int c = (int)(idx / NV);
    const float* w; int lc;
    if (c < 64)       { w = w0; lc = c; }
    else if (c < 192) { w = w1; lc = c - 64; }
    else if (c < 448) { w = w2; lc = c - 192; }
    else              { w = w3; lc = c - 448; }
    int ri = is64 ? roi[2 * v] : roi[v];
    g_wsel[(size_t)c * NV + v] = w[(size_t)lc * NVT + (size_t)ri];
}

// ---------------- fused single-pass fp16 mma.sync GEMM (R8 config — best known) ----------------
// BM=128, BN=128, BK=32; 8 warps as 4(m) x 2(n), warp tile 32x64;
// 4-stage cp.async pipeline, one __syncthreads per k-iteration.

#define STAGE_BYTES 16384
#define A_HI_OFF 0
#define B_HI_OFF 8192
#define SMEM_TOTAL (4 * STAGE_BYTES)   // 64 KB

__device__ __forceinline__ uint32_t smem_u32(const void* p) {
    uint32_t a;
    asm("{ .reg .u64 t; cvta.to.shared.u64 t, %1; cvt.u32.u64 %0, t; }" : "=r"(a) : "l"(p));
    return a;
}
__device__ __forceinline__ uint32_t swz(uint32_t base, int row, int chunk) {
    return base + (uint32_t)(row * 64 + (chunk ^ ((row >> 1) & 3)) * 16);
}
__device__ __forceinline__ void cp16(uint32_t dst, const void* src, bool v) {
    asm volatile("cp.async.cg.shared.global [%0], [%1], 16, %2;"
                 :: "r"(dst), "l"(src), "r"(v ? 16 : 0));
}
#define CP_COMMIT() asm volatile("cp.async.commit_group;" ::: "memory")
#define CP_WAIT2()  asm volatile("cp.async.wait_group 2;" ::: "memory")

#define LDSM4(r0, r1, r2, r3, a) \
    asm volatile("ldmatrix.sync.aligned.m8n8.x4.shared.b16 {%0,%1,%2,%3}, [%4];" \
                 : "=r"(r0), "=r"(r1), "=r"(r2), "=r"(r3) : "r"(a))

#define MMA(d, a, b0_, b1_) \
    asm volatile("mma.sync.aligned.m16n8k16.row.col.f32.f16.f16.f32 " \
                 "{%0,%1,%2,%3}, {%4,%5,%6,%7}, {%8,%9}, {%0,%1,%2,%3};" \
                 : "+f"((d)[0]), "+f"((d)[1]), "+f"((d)[2]), "+f"((d)[3]) \
                 : "r"((a)[0]), "r"((a)[1]), "r"((a)[2]), "r"((a)[3]), "r"(b0_), "r"(b1_))

__global__ void __launch_bounds__(256, 2)
gemm_all(float* __restrict__ out)
{
    extern __shared__ char smem[];
    const uint32_t sb = smem_u32(smem);
    const int tid = threadIdx.x;
    const int lane = tid & 31;
    const int w = tid >> 5;
    const int wm = w >> 1;          // 0..3 (m)
    const int wn = w & 1;           // 0..1 (n)

    const int t = blockIdx.x;
    int Kpad, cShift, cOff, mtiles, base; size_t aOff, bOff;
    if (t < 252)       { base = 0;    mtiles = 4;  Kpad = 3136; aOff = 0;       bOff = 0;        cShift = 6; cOff = 0; }
    else if (t < 756)  { base = 252;  mtiles = 8;  Kpad = 800;  aOff = 1605632; bOff = 25088000; cShift = 7; cOff = 64; }
    else if (t < 1764) { base = 756;  mtiles = 16; Kpad = 224;  aOff = 2424832; bOff = 31488000; cShift = 8; cOff = 192; }
    else               { base = 1764; mtiles = 32; Kpad = 64;   aOff = 2883584; bOff = 33280000; cShift = 9; cOff = 448; }
    const int local = t - base;
    const int bm = (local % mtiles) * 128;
    const int bn = (local / mtiles) * 128;

    const __half* __restrict__ Ahi = g_ahi + aOff;
    const __half* __restrict__ Bhi = g_bhi + bOff;

    const int nkt = Kpad >> 5;

    auto load_stage = [&](int kt, int buf) {
        const uint32_t s = sb + buf * STAGE_BYTES;
        const int k0 = kt << 5;
#pragma unroll
        for (int hh = 0; hh < 2; hh++) {
            int cid = hh * 256 + tid;
            int row = cid >> 2, ch = cid & 3;
            size_t ga = (size_t)(bm + row) * Kpad + k0 + ch * 8;
            cp16(swz(s + A_HI_OFF, row, ch), Ahi + ga, true);
            int n = bn + row;
            bool v = n < NV;
            size_t gb = v ? ((size_t)n * Kpad + k0 + ch * 8) : 0;
            cp16(swz(s + B_HI_OFF, row, ch), Bhi + gb, v);
        }
    };

    float acc[2][8][4];
#pragma unroll
    for (int i = 0; i < 2; i++)
#pragma unroll
        for (int j = 0; j < 8; j++)
#pragma unroll
            for (int q = 0; q < 4; q++) acc[i][j][q] = 0.0f;

    load_stage(0, 0); CP_COMMIT();
    if (nkt > 1) load_stage(1, 1);
    CP_COMMIT();
    if (nkt > 2) load_stage(2, 2);
    CP_COMMIT();

    const int mid = lane >> 3, r8 = lane & 7;

    for (int kt = 0; kt < nkt; kt++) {
        CP_WAIT2();
        __syncthreads();
        if (kt + 3 < nkt) load_stage(kt + 3, (kt + 3) & 3);
        CP_COMMIT();

        const uint32_t s = sb + (kt & 3) * STAGE_BYTES;
#pragma unroll
        for (int ks = 0; ks < 2; ks++) {
            uint32_t ah[2][4], bh[4][4];
            int arow = wm * 32 + (mid & 1) * 8 + r8;
            int ach = ks * 2 + (mid >> 1);
#pragma unroll
            for (int mi = 0; mi < 2; mi++)
                LDSM4(ah[mi][0], ah[mi][1], ah[mi][2], ah[mi][3], swz(s + A_HI_OFF, arow + mi * 16, ach));
            int brow = wn * 64 + (mid >> 1) * 8 + r8;
            int bch = ks * 2 + (mid & 1);
#pragma unroll
            for (int nj = 0; nj < 4; nj++)
                LDSM4(bh[nj][0], bh[nj][1], bh[nj][2], bh[nj][3], swz(s + B_HI_OFF, brow + nj * 16, bch));
#pragma unroll
            for (int mi = 0; mi < 2; mi++) {
#pragma unroll
                for (int ni = 0; ni < 8; ni++) {
                    uint32_t* bp = &bh[ni >> 1][(ni & 1) * 2];
                    MMA(acc[mi][ni], ah[mi], bp[0], bp[1]);
                }
            }
        }
    }

    const int tg = lane >> 2, tq = lane & 3;
    const int Cm1 = (1 << cShift) - 1;
#pragma unroll
    for (int mi = 0; mi < 2; mi++) {
#pragma unroll
        for (int h = 0; h < 2; h++) {
            int m = bm + wm * 32 + mi * 16 + h * 8 + tg;
            int bI = m >> cShift;
            int c = m & Cm1;
            float* orow = out + ((size_t)bI * C_TOTAL + cOff + c) * NV;
            const float* wrow = g_wsel + (size_t)(cOff + c) * NV;
#pragma unroll
            for (int ni = 0; ni < 8; ni++) {
                int col = bn + wn * 64 + ni * 8 + tq * 2;
                if (col < NV) {
                    float2 wv = *(const float2*)(wrow + col);
                    float2 o;
                    o.x = acc[mi][ni][h * 2 + 0] * wv.x;
                    o.y = acc[mi][ni][h * 2 + 1] * wv.y;
                    *(float2*)(orow + col) = o;
                }
            }
        }
    }
}

// ---------------- launch ----------------
extern "C" void kernel_launch(void* const* d_in, const int* in_sizes, int n_in,
                              void* d_out, int out_size) {
    static const int fsz[4] = {1605632, 802816, 401408, 200704};
    static const int rsz[4] = {62720000, 15680000, 3920000, 980000};
    static const int wsz[4] = {1280000, 2560000, 5120000, 10240000};

    const float* fmap[4] = {0, 0, 0, 0};
    const float* rfp[4]  = {0, 0, 0, 0};
    const float* wptr[4] = {0, 0, 0, 0};
    const int*   roi = 0;

    for (int i = 0; i < n_in; i++) {
        int s = in_sizes[i];
        if (s == NV) { roi = (const int*)d_in[i]; continue; }
        for (int l = 0; l < 4; l++) {
            if (s == fsz[l]) fmap[l] = (const float*)d_in[i];
            else if (s == rsz[l]) rfp[l]  = (const float*)d_in[i];
            else if (s == wsz[l]) wptr[l] = (const float*)d_in[i];
        }
    }

    float* out = (float*)d_out;

    cudaFuncSetAttribute(gemm_all, cudaFuncAttributeMaxDynamicSharedMemorySize, SMEM_TOTAL);

    split_all<<<A_ELEMS / 256, 256>>>(fmap[0], fmap[1], fmap[2], fmap[3]);          // 1
    gather_tr_all<<<dim3(132, 32), 256>>>(rfp[0], rfp[1], rfp[2], rfp[3], roi);     // 2
    gather_w_all<<<(int)(((long long)C_TOTAL * NV + 255) / 256), 256>>>(            // 3
        wptr[0], wptr[1], wptr[2], wptr[3], roi);
    gemm_all<<<3780, 256, SMEM_TOTAL>>>(out);                                        // 4 <- profiled
}

// round 12
// speedup vs baseline: 1.4044x; 1.1049x over previous
#include <cuda_runtime.h>
#include <cuda_fp16.h>
#include <cstdint>

#define NV 8000
#define NVT 20000
#define C_TOTAL 960
// Kpad multiples of 64: {3136, 832, 256, 64}
#define KPAD_SUM 4288
#define A_ELEMS 3244032   // 512*3136 + 1024*832 + 2048*256 + 4096*64

// ---------------- scratch (__device__ globals; allocation-free rule) ----------------
__device__ __align__(16) __half g_a[A_ELEMS];                    // fp16 fmap [M, Kpad]
__device__ __align__(16) __half g_b[(size_t)KPAD_SUM * NV];      // [Kpad, 8000] v-major fp16
__device__ __align__(16) float g_wsel[(size_t)C_TOTAL * NV];

// ---------------- roi dtype detect (int64 vs int32; values < 20000) ----------------
__device__ __forceinline__ bool roi_is64(const int* __restrict__ r32) {
    int acc = 0;
#pragma unroll
    for (int i = 1; i < 32; i += 2) acc |= r32[i];
    return acc == 0;
}

// ---------------- prep kernels ----------------
// fmap fp32 -> g_a fp16, zero-padded (split in two for launch ordering)
__device__ __forceinline__ void split_one(int idx, const float* f, int K, int Kpad, int base) {
    int local = idx - base;
    int m = local / Kpad, k = local - m * Kpad;
    float x = (k < K) ? f[(size_t)m * K + k] : 0.0f;
    g_a[idx] = __float2half_rn(x);
}
__global__ void split01(const float* __restrict__ f0, const float* __restrict__ f1) {
    int idx = blockIdx.x * 256 + threadIdx.x;
    if (idx < 1605632)      split_one(idx, f0, 3136, 3136, 0);
    else if (idx < 2457600) split_one(idx, f1, 784, 832, 1605632);
}
__global__ void split23(const float* __restrict__ f2, const float* __restrict__ f3) {
    int idx = 2457600 + blockIdx.x * 256 + threadIdx.x;
    if (idx < 2981888)      split_one(idx, f2, 196, 256, 2457600);
    else if (idx < A_ELEMS) split_one(idx, f3, 49, 64, 2981888);
}

// w gather; all layers, flat over 960 x 8000 rows
__global__ void gather_w_all(const float* __restrict__ w0, const float* __restrict__ w1,
                             const float* __restrict__ w2, const float* __restrict__ w3,
                             const int* __restrict__ roi) {
    const bool is64 = roi_is64(roi);
    long long idx = (long long)blockIdx.x * 256 + threadIdx.x;
    if (idx >= (long long)C_TOTAL * NV) return;
    int v = (int)(idx % NV);
    int c = (int)(idx / NV);
    const float* w; int lc;
    if (c < 64)       { w = w0; lc = c; }
    else if (c < 192) { w = w1; lc = c - 64; }
    else if (c < 448) { w = w2; lc = c - 192; }
    else              { w = w3; lc = c - 448; }
    int ri = is64 ? roi[2 * v] : roi[v];
    g_wsel[(size_t)c * NV + v] = w[(size_t)lc * NVT + (size_t)ri];
}

// Direct v-major gather: g_b[kp][v] = fp16(leaky_relu(rf[kp][roi[v]])).
// No transpose, no smem: reads AND writes are v-contiguous.
// Each block: 8 kp-rows x 256 v; each thread: roi once + 8 independent LDGs.
#define KPG 8
__global__ void gather_b_all(const float* __restrict__ r0, const float* __restrict__ r1,
                             const float* __restrict__ r2, const float* __restrict__ r3,
                             const int* __restrict__ roi) {
    const int g = blockIdx.x;
    const float* rf; int K, kp0; size_t bOff;
    if (g < 392)      { rf = r0; K = 3136; bOff = 0;        kp0 = g * KPG; }
    else if (g < 496) { rf = r1; K = 784;  bOff = 25088000; kp0 = (g - 392) * KPG; }
    else if (g < 528) { rf = r2; K = 196;  bOff = 31744000; kp0 = (g - 496) * KPG; }
    else              { rf = r3; K = 49;   bOff = 33792000; kp0 = (g - 528) * KPG; }
    const int v = blockIdx.y * 256 + threadIdx.x;
    if (v >= NV) return;
    const bool is64 = roi_is64(roi);
    const int ri = is64 ? roi[2 * v] : roi[v];
    const float* col = rf + ri;

    float x[KPG];
#pragma unroll
    for (int i = 0; i < KPG; i++) {
        int kp = kp0 + i;
        x[i] = (kp < K) ? __ldg(col + (size_t)kp * NVT) : 0.0f;
    }
#pragma unroll
    for (int i = 0; i < KPG; i++) {
        float a = x[i];
        a = (a > 0.0f) ? a : 0.01f * a;
        g_b[bOff + (size_t)(kp0 + i) * NV + v] = __float2half_rn(a);
    }
}

// ---------------- fused fp16 mma.sync GEMM (R9 config: v-major B, BK=64) ----------------
// out[b, c, v] = (A @ B)[m, v] * wsel ; BM=128, BN=128, BK=64; 8 warps 4(m)x2(n) 32x64;
// 3-stage cp.async pipeline; B frags via ldmatrix.trans.

#define STAGE_BYTES 32768
#define A_OFF 0          // 128 rows x 128B
#define B_OFF 16384      // 64 rows x 256B
#define SMEM_TOTAL (3 * STAGE_BYTES)   // 96 KB

__device__ __forceinline__ uint32_t smem_u32(const void* p) {
    uint32_t a;
    asm("{ .reg .u64 t; cvta.to.shared.u64 t, %1; cvt.u32.u64 %0, t; }" : "=r"(a) : "l"(p));
    return a;
}
__device__ __forceinline__ uint32_t swzA(uint32_t base, int row, int chunk) {
    return base + (uint32_t)(row * 128 + (chunk ^ (row & 7)) * 16);
}
__device__ __forceinline__ uint32_t swzB(uint32_t base, int row, int chunk) {
    return base + (uint32_t)(row * 256 + (chunk ^ (row & 7)) * 16);
}
__device__ __forceinline__ void cp16(uint32_t dst, const void* src, bool v) {
    asm volatile("cp.async.cg.shared.global [%0], [%1], 16, %2;"
                 :: "r"(dst), "l"(src), "r"(v ? 16 : 0));
}
#define CP_COMMIT() asm volatile("cp.async.commit_group;" ::: "memory")
#define CP_WAIT1()  asm volatile("cp.async.wait_group 1;" ::: "memory")

#define LDSM4(r0, r1, r2, r3, a) \
    asm volatile("ldmatrix.sync.aligned.m8n8.x4.shared.b16 {%0,%1,%2,%3}, [%4];" \
                 : "=r"(r0), "=r"(r1), "=r"(r2), "=r"(r3) : "r"(a))
#define LDSM4T(r0, r1, r2, r3, a) \
    asm volatile("ldmatrix.sync.aligned.m8n8.x4.trans.shared.b16 {%0,%1,%2,%3}, [%4];" \
                 : "=r"(r0), "=r"(r1), "=r"(r2), "=r"(r3) : "r"(a))

#define MMA(d, a, b0_, b1_) \
    asm volatile("mma.sync.aligned.m16n8k16.row.col.f32.f16.f16.f32 " \
                 "{%0,%1,%2,%3}, {%4,%5,%6,%7}, {%8,%9}, {%0,%1,%2,%3};" \
                 : "+f"((d)[0]), "+f"((d)[1]), "+f"((d)[2]), "+f"((d)[3]) \
                 : "r"((a)[0]), "r"((a)[1]), "r"((a)[2]), "r"((a)[3]), "r"(b0_), "r"(b1_))

__global__ void __launch_bounds__(256, 2)
gemm_all(float* __restrict__ out)
{
    extern __shared__ char smem[];
    const uint32_t sb = smem_u32(smem);
    const int tid = threadIdx.x;
    const int lane = tid & 31;
    const int w = tid >> 5;
    const int wm = w >> 1;          // 0..3 (m)
    const int wn = w & 1;           // 0..1 (n)

    const int t = blockIdx.x;
    int Kpad, cShift, cOff, mtiles, base; size_t aOff, bOff;
    if (t < 252)       { base = 0;    mtiles = 4;  Kpad = 3136; aOff = 0;       bOff = 0;        cShift = 6; cOff = 0; }
    else if (t < 756)  { base = 252;  mtiles = 8;  Kpad = 832;  aOff = 1605632; bOff = 25088000; cShift = 7; cOff = 64; }
    else if (t < 1764) { base = 756;  mtiles = 16; Kpad = 256;  aOff = 2457600; bOff = 31744000; cShift = 8; cOff = 192; }
    else               { base = 1764; mtiles = 32; Kpad = 64;   aOff = 2981888; bOff = 33792000; cShift = 9; cOff = 448; }
    const int local = t - base;
    const int bm = (local % mtiles) * 128;
    const int bn = (local / mtiles) * 128;

    const __half* __restrict__ A = g_a + aOff;
    const __half* __restrict__ B = g_b + bOff;

    const int nkt = Kpad >> 6;

    auto load_stage = [&](int kt, int buf) {
        const uint32_t s = sb + buf * STAGE_BYTES;
        const int k0 = kt << 6;
#pragma unroll
        for (int q = 0; q < 4; q++) {
            int cid = q * 256 + tid;
            int ar = cid >> 3, ac = cid & 7;
            cp16(swzA(s + A_OFF, ar, ac), A + (size_t)(bm + ar) * Kpad + k0 + ac * 8, true);
            int br = cid >> 4, bc = cid & 15;
            int n = bn + bc * 8;
            cp16(swzB(s + B_OFF, br, bc), B + (size_t)(k0 + br) * NV + n, n < NV);
        }
    };

    float acc[2][8][4];
#pragma unroll
    for (int i = 0; i < 2; i++)
#pragma unroll
        for (int j = 0; j < 8; j++)
#pragma unroll
            for (int q = 0; q < 4; q++) acc[i][j][q] = 0.0f;

    load_stage(0, 0); CP_COMMIT();
    if (nkt > 1) load_stage(1, 1);
    CP_COMMIT();

    const int mid = lane >> 3, r8 = lane & 7;
    int buf = 0;

    for (int kt = 0; kt < nkt; kt++) {
        CP_WAIT1();
        __syncthreads();
        if (kt + 2 < nkt) {
            int nb = buf + 2; if (nb >= 3) nb -= 3;
            load_stage(kt + 2, nb);
        }
        CP_COMMIT();

        const uint32_t s = sb + buf * STAGE_BYTES;
#pragma unroll
        for (int ks = 0; ks < 4; ks++) {
            uint32_t ah[2][4], bh[4][4];
            int arow = wm * 32 + (mid & 1) * 8 + r8;
            int ach = ks * 2 + (mid >> 1);
#pragma unroll
            for (int mi = 0; mi < 2; mi++)
                LDSM4(ah[mi][0], ah[mi][1], ah[mi][2], ah[mi][3],
                      swzA(s + A_OFF, arow + mi * 16, ach));
            int brow = ks * 16 + (mid & 1) * 8 + r8;
#pragma unroll
            for (int nj = 0; nj < 4; nj++) {
                int bch = wn * 8 + nj * 2 + (mid >> 1);
                LDSM4T(bh[nj][0], bh[nj][1], bh[nj][2], bh[nj][3],
                       swzB(s + B_OFF, brow, bch));
            }
#pragma unroll
            for (int mi = 0; mi < 2; mi++) {
#pragma unroll
                for (int ni = 0; ni < 8; ni++) {
                    uint32_t* bp = &bh[ni >> 1][(ni & 1) * 2];
                    MMA(acc[mi][ni], ah[mi], bp[0], bp[1]);
                }
            }
        }
        buf++; if (buf == 3) buf = 0;
    }

    const int tg = lane >> 2, tq = lane & 3;
    const int Cm1 = (1 << cShift) - 1;
#pragma unroll
    for (int mi = 0; mi < 2; mi++) {
#pragma unroll
        for (int h = 0; h < 2; h++) {
            int m = bm + wm * 32 + mi * 16 + h * 8 + tg;
            int bI = m >> cShift;
            int c = m & Cm1;
            float* orow = out + ((size_t)bI * C_TOTAL + cOff + c) * NV;
            const float* wrow = g_wsel + (size_t)(cOff + c) * NV;
#pragma unroll
            for (int ni = 0; ni < 8; ni++) {
                int col = bn + wn * 64 + ni * 8 + tq * 2;
                if (col < NV) {
                    float2 wv = *(const float2*)(wrow + col);
                    float2 o;
                    o.x = acc[mi][ni][h * 2 + 0] * wv.x;
                    o.y = acc[mi][ni][h * 2 + 1] * wv.y;
                    *(float2*)(orow + col) = o;
                }
            }
        }
    }
}

// ---------------- launch ----------------
extern "C" void kernel_launch(void* const* d_in, const int* in_sizes, int n_in,
                              void* d_out, int out_size) {
    static const int fsz[4] = {1605632, 802816, 401408, 200704};
    static const int rsz[4] = {62720000, 15680000, 3920000, 980000};
    static const int wsz[4] = {1280000, 2560000, 5120000, 10240000};

    const float* fmap[4] = {0, 0, 0, 0};
    const float* rfp[4]  = {0, 0, 0, 0};
    const float* wptr[4] = {0, 0, 0, 0};
    const int*   roi = 0;

    for (int i = 0; i < n_in; i++) {
        int s = in_sizes[i];
        if (s == NV) { roi = (const int*)d_in[i]; continue; }
        for (int l = 0; l < 4; l++) {
            if (s == fsz[l]) fmap[l] = (const float*)d_in[i];
            else if (s == rsz[l]) rfp[l]  = (const float*)d_in[i];
            else if (s == wsz[l]) wptr[l] = (const float*)d_in[i];
        }
    }

    float* out = (float*)d_out;

    cudaFuncSetAttribute(gemm_all, cudaFuncAttributeMaxDynamicSharedMemorySize, SMEM_TOTAL);

    split01<<<2457600 / 256, 256>>>(fmap[0], fmap[1]);                               // 1
    split23<<<(A_ELEMS - 2457600) / 256, 256>>>(fmap[2], fmap[3]);                   // 2
    gather_w_all<<<(int)(((long long)C_TOTAL * NV + 255) / 256), 256>>>(             // 3
        wptr[0], wptr[1], wptr[2], wptr[3], roi);
    gather_b_all<<<dim3(536, 32), 256>>>(rfp[0], rfp[1], rfp[2], rfp[3], roi);       // 4 <- profiled
    gemm_all<<<3780, 256, SMEM_TOTAL>>>(out);                                         // 5
}